// round 9
// baseline (speedup 1.0000x reference)
#include <cuda_runtime.h>
#include <cuda_bf16.h>
#include <cstdint>

// Problem constants
static constexpr int TOK    = 4096;   // B*S
static constexpr int SEQ    = 2048;
static constexpr int DMODEL = 1024;
static constexpr int DFFN   = 4096;

// ---------------------------------------------------------------------------
// Device scratch (allocation-free rule: __device__ globals)
// ---------------------------------------------------------------------------
__device__ __nv_bfloat16 g_srcB [(size_t)TOK * DMODEL];
__device__ __nv_bfloat16 g_Wqkv [(size_t)DMODEL * 3 * DMODEL];  // [1024][3072] row-major
__device__ float         g_bqkv [3 * DMODEL];
__device__ __nv_bfloat16 g_WoB  [(size_t)DMODEL * DMODEL];
__device__ __nv_bfloat16 g_W1B  [(size_t)DMODEL * DFFN];
__device__ __nv_bfloat16 g_W2B  [(size_t)DFFN * DMODEL];
__device__ __nv_bfloat16 g_QKV  [(size_t)TOK * 3 * DMODEL];     // [4096][3072]
__device__ __nv_bfloat16 g_C    [(size_t)TOK * DMODEL];         // ctx (bf16)
__device__ __nv_bfloat16 g_X1B  [(size_t)TOK * DMODEL];         // bf16 LN1 out
__device__ __nv_bfloat16 g_H    [(size_t)TOK * DFFN];           // bf16 relu(xW1+b1)
__device__ float g_AO[(size_t)TOK * DMODEL];                    // fp32 attn_out
__device__ float g_X1[(size_t)TOK * DMODEL];                    // fp32 LN1 out
__device__ float g_FF[(size_t)TOK * DMODEL];                    // fp32 ff out

// Single dynamic-smem declaration shared by all kernels
extern __shared__ __align__(16) char dsmem[];

// ---------------------------------------------------------------------------
// Helpers
// ---------------------------------------------------------------------------
__device__ __forceinline__ uint32_t packbf(float lo, float hi) {
    uint32_t r;
    asm("cvt.rn.bf16x2.f32 %0, %1, %2;" : "=r"(r) : "f"(hi), "f"(lo));
    return r;
}
__device__ __forceinline__ void cp16(void* s, const void* g) {
    uint32_t sa = (uint32_t)__cvta_generic_to_shared(s);
    asm volatile("cp.async.cg.shared.global [%0], [%1], 16;" :: "r"(sa), "l"(g));
}
__device__ __forceinline__ void cp_commit() { asm volatile("cp.async.commit_group;"); }
template <int N> __device__ __forceinline__ void cp_wait() {
    asm volatile("cp.async.wait_group %0;" :: "n"(N));
}
__device__ __forceinline__ void ldsm4(uint32_t* r, const void* p) {
    uint32_t a = (uint32_t)__cvta_generic_to_shared(p);
    asm volatile("ldmatrix.sync.aligned.m8n8.x4.shared.b16 {%0,%1,%2,%3}, [%4];"
                 : "=r"(r[0]), "=r"(r[1]), "=r"(r[2]), "=r"(r[3]) : "r"(a));
}
__device__ __forceinline__ void ldsm4t(uint32_t* r, const void* p) {
    uint32_t a = (uint32_t)__cvta_generic_to_shared(p);
    asm volatile("ldmatrix.sync.aligned.m8n8.x4.trans.shared.b16 {%0,%1,%2,%3}, [%4];"
                 : "=r"(r[0]), "=r"(r[1]), "=r"(r[2]), "=r"(r[3]) : "r"(a));
}
__device__ __forceinline__ void mma16(float* c, const uint32_t* a, const uint32_t* b) {
    asm volatile(
        "mma.sync.aligned.m16n8k16.row.col.f32.bf16.bf16.f32 "
        "{%0,%1,%2,%3},{%4,%5,%6,%7},{%8,%9},{%0,%1,%2,%3};"
        : "+f"(c[0]), "+f"(c[1]), "+f"(c[2]), "+f"(c[3])
        : "r"(a[0]), "r"(a[1]), "r"(a[2]), "r"(a[3]), "r"(b[0]), "r"(b[1]));
}
__device__ __forceinline__ float bred_sum(float v) {
    __shared__ float sh[8];
    #pragma unroll
    for (int o = 16; o > 0; o >>= 1) v += __shfl_xor_sync(0xffffffffu, v, o);
    if ((threadIdx.x & 31) == 0) sh[threadIdx.x >> 5] = v;
    __syncthreads();
    float r = sh[0];
    #pragma unroll
    for (int i = 1; i < 8; i++) r += sh[i];
    __syncthreads();
    return r;
}

// ---------------------------------------------------------------------------
// Converters
// ---------------------------------------------------------------------------
__global__ void __launch_bounds__(256)
cvt_bf16(const float* __restrict__ in, __nv_bfloat16* __restrict__ out,
         int n4, float scale)
{
    for (int i = blockIdx.x * 256 + threadIdx.x; i < n4; i += gridDim.x * 256) {
        float4 v = ((const float4*)in)[i];
        uint2 u;
        u.x = packbf(v.x * scale, v.y * scale);
        u.y = packbf(v.z * scale, v.w * scale);
        ((uint2*)out)[i] = u;
    }
}
// Concatenate Wq|Wk|Wv ([1024][1024] each) into [1024][3072] bf16 (Wq scaled).
__global__ void __launch_bounds__(256)
cvt_cat3(const float* __restrict__ Wq, const float* __restrict__ Wk,
         const float* __restrict__ Wv, __nv_bfloat16* __restrict__ out)
{
    const int z = blockIdx.y;                       // matrix select
    const float* in = (z == 0) ? Wq : (z == 1) ? Wk : Wv;
    const float scale = (z == 0) ? 0.125f : 1.f;
    for (int i = blockIdx.x * 256 + threadIdx.x; i < 1024 * 256; i += gridDim.x * 256) {
        int r = i >> 8, c4 = i & 255;               // row, float4-col
        float4 v = ((const float4*)(in + (size_t)r * 1024))[c4];
        uint2 u;
        u.x = packbf(v.x * scale, v.y * scale);
        u.y = packbf(v.z * scale, v.w * scale);
        ((uint2*)(out + (size_t)r * 3072 + z * 1024))[c4] = u;
    }
}
__global__ void __launch_bounds__(256)
bias_qkv(const float* __restrict__ bq, const float* __restrict__ bk,
         const float* __restrict__ bv, float* __restrict__ o)
{
    int i = blockIdx.x * 256 + threadIdx.x;
    if (i < 1024)       o[i] = bq[i] * 0.125f;
    else if (i < 2048)  o[i] = bk[i - 1024];
    else if (i < 3072)  o[i] = bv[i - 2048];
}

// ---------------------------------------------------------------------------
// BF16 GEMM v2.  C[M,N] = epi( A[M,K]*B + bias ).  A row-major, B [K,N] row-major.
// BM=128 BN=256 BK=64, 8 warps (warp tile 64x64), 3-stage cp.async ring.
// 32 FLOP per LDS byte (2x round-5) -> crossbar no longer binding.
// ---------------------------------------------------------------------------
static constexpr int G2_LDA = 72;               // bf16/row: 144B = 16 mod 128
static constexpr int G2_LDB = 264;              // bf16/row: 528B = 16 mod 128
static constexpr int G2_ASZ = 128 * G2_LDA;     // elements
static constexpr int G2_BSZ = 64 * G2_LDB;
static constexpr int G2_STAGE = G2_ASZ + G2_BSZ;        // elements per stage
static constexpr int G2_SMEM  = 3 * G2_STAGE * 2;       // 156672 B

template <bool RELU, bool OBF>
__global__ void __launch_bounds__(256)
gemm_b2(const __nv_bfloat16* __restrict__ A, const __nv_bfloat16* __restrict__ B,
        const float* __restrict__ bias, void* __restrict__ Cv,
        int Kdim, int lda, int ldb, int ldc)
{
    __nv_bfloat16* smem = (__nv_bfloat16*)dsmem;

    const int m0 = blockIdx.y * 128, n0 = blockIdx.x * 256;
    const int tid = threadIdx.x, w = tid >> 5, l = tid & 31;
    const int wm = (w & 1) * 64, wn = (w >> 1) * 64;
    const int g = l >> 3, i8 = l & 7;
    const int lr = l >> 2, lq = l & 3;

    float acc[4][8][4];
    #pragma unroll
    for (int i = 0; i < 4; i++)
        #pragma unroll
        for (int j = 0; j < 8; j++)
            #pragma unroll
            for (int q = 0; q < 4; q++) acc[i][j][q] = 0.f;

    const int NS = Kdim / 64;

    auto load_stage = [&](int s) {
        __nv_bfloat16* dA = smem + (s % 3) * G2_STAGE;
        __nv_bfloat16* dB = dA + G2_ASZ;
        {   // A tile [128][64]: 1024 chunks / 256 thr = 4
            const __nv_bfloat16* gA = A + (size_t)m0 * lda + s * 64;
            #pragma unroll
            for (int i = 0; i < 4; i++) {
                int idx = tid + i * 256;
                int r = idx >> 3, c = (idx & 7) * 8;
                cp16(&dA[r * G2_LDA + c], gA + (size_t)r * lda + c);
            }
        }
        {   // B tile [64][256]: 2048 chunks / 256 thr = 8
            const __nv_bfloat16* gB = B + (size_t)s * 64 * ldb + n0;
            #pragma unroll
            for (int i = 0; i < 8; i++) {
                int idx = tid + i * 256;
                int r = idx >> 5, c = (idx & 31) * 8;
                cp16(&dB[r * G2_LDB + c], gB + (size_t)r * ldb + c);
            }
        }
    };

    load_stage(0); cp_commit();
    load_stage(1); cp_commit();
    load_stage(2); cp_commit();

    for (int s = 0; s < NS; s++) {
        cp_wait<2>();
        __syncthreads();

        const __nv_bfloat16* cA = smem + (s % 3) * G2_STAGE;
        const __nv_bfloat16* cB = cA + G2_ASZ;
        #pragma unroll
        for (int t = 0; t < 4; t++) {           // k16 steps within BK=64
            uint32_t af[4][4], bf[4][4];
            #pragma unroll
            for (int i = 0; i < 4; i++) {       // m-blocks of 16
                int r = wm + i * 16 + (g & 1) * 8 + i8;
                int c = t * 16 + (g >> 1) * 8;
                ldsm4(af[i], &cA[r * G2_LDA + c]);
            }
            #pragma unroll
            for (int p = 0; p < 4; p++) {       // n-blocks of 16
                int r = t * 16 + (g & 1) * 8 + i8;
                int c = wn + p * 16 + (g >> 1) * 8;
                ldsm4t(bf[p], &cB[r * G2_LDB + c]);
            }
            #pragma unroll
            for (int i = 0; i < 4; i++)
                #pragma unroll
                for (int p = 0; p < 4; p++) {
                    mma16(acc[i][2 * p],     af[i], &bf[p][0]);
                    mma16(acc[i][2 * p + 1], af[i], &bf[p][2]);
                }
        }
        __syncthreads();
        if (s + 3 < NS) load_stage(s + 3);
        cp_commit();
    }

    // Epilogue
    #pragma unroll
    for (int i = 0; i < 4; i++) {
        #pragma unroll
        for (int j = 0; j < 8; j++) {
            int r = m0 + wm + i * 16 + lr;
            int c = n0 + wn + j * 8 + lq * 2;
            float b0 = bias[c], b1 = bias[c + 1];
            float v0 = acc[i][j][0] + b0;
            float v1 = acc[i][j][1] + b1;
            float v2 = acc[i][j][2] + b0;
            float v3 = acc[i][j][3] + b1;
            if constexpr (RELU) {
                v0 = fmaxf(v0, 0.f); v1 = fmaxf(v1, 0.f);
                v2 = fmaxf(v2, 0.f); v3 = fmaxf(v3, 0.f);
            }
            if constexpr (OBF) {
                __nv_bfloat16* Cb = (__nv_bfloat16*)Cv;
                *(uint32_t*)&Cb[(size_t)r * ldc + c]       = packbf(v0, v1);
                *(uint32_t*)&Cb[(size_t)(r + 8) * ldc + c] = packbf(v2, v3);
            } else {
                float* Cf = (float*)Cv;
                *(float2*)&Cf[(size_t)r * ldc + c]       = make_float2(v0, v1);
                *(float2*)&Cf[(size_t)(r + 8) * ldc + c] = make_float2(v2, v3);
            }
        }
    }
}

// ---------------------------------------------------------------------------
// Fused flash attention (bf16, legacy mma). 512 threads / 16 warps,
// 256 q-rows per block. ldq = row stride of fused QKV buffer (3072).
// ---------------------------------------------------------------------------
static constexpr int FA_LD = 72;
static constexpr int FA_SMEM = (2 * 64 * FA_LD + 2 * 64 * FA_LD + 256 * FA_LD) * 2;

__global__ void __launch_bounds__(512)
fa_kernel(const __nv_bfloat16* __restrict__ QKV, __nv_bfloat16* __restrict__ C, int ldq)
{
    constexpr int NIT = SEQ / 64;
    __nv_bfloat16* smem = (__nv_bfloat16*)dsmem;
    __nv_bfloat16* sK = smem;
    __nv_bfloat16* sV = smem + 2 * 64 * FA_LD;
    __nv_bfloat16* sQ = smem + 4 * 64 * FA_LD;

    const int z = blockIdx.y;
    const int b = z >> 4, h = z & 15;
    const int q0 = blockIdx.x * 256;
    const __nv_bfloat16* Qg = QKV + (size_t)(b * SEQ + q0) * ldq + h * 64;
    const __nv_bfloat16* Kg = QKV + (size_t)(b * SEQ) * ldq + 1024 + h * 64;
    const __nv_bfloat16* Vg = QKV + (size_t)(b * SEQ) * ldq + 2048 + h * 64;

    const int tid = threadIdx.x, w = tid >> 5, l = tid & 31;
    const int g = l >> 3, i8 = l & 7;
    const int lr = l >> 2, lq = l & 3;

    auto loadKV = [&](int n0, int buf) {
        __nv_bfloat16* dK = sK + buf * 64 * FA_LD;
        __nv_bfloat16* dV = sV + buf * 64 * FA_LD;
        int r = tid >> 3, c = (tid & 7) * 8;
        cp16(&dK[r * FA_LD + c], Kg + (size_t)(n0 + r) * ldq + c);
        cp16(&dV[r * FA_LD + c], Vg + (size_t)(n0 + r) * ldq + c);
    };

    #pragma unroll
    for (int i = 0; i < 4; i++) {
        int idx = tid + i * 512;
        int r = idx >> 3, c = (idx & 7) * 8;
        cp16(&sQ[r * FA_LD + c], Qg + (size_t)r * ldq + c);
    }
    cp_commit();
    loadKV(0, 0);
    cp_commit();

    cp_wait<1>();
    __syncthreads();

    uint32_t qf[4][4];
    #pragma unroll
    for (int t = 0; t < 4; t++) {
        int r = w * 16 + (g & 1) * 8 + i8;
        int c = t * 16 + (g >> 1) * 8;
        ldsm4(qf[t], &sQ[r * FA_LD + c]);
    }

    float oacc[8][4];
    #pragma unroll
    for (int j = 0; j < 8; j++)
        #pragma unroll
        for (int q = 0; q < 4; q++) oacc[j][q] = 0.f;
    float mA = -1e30f, mB = -1e30f, lA = 0.f, lB = 0.f;

    for (int it = 0; it < NIT; it++) {
        const int buf = it & 1;
        __syncthreads();
        if (it + 1 < NIT) {
            loadKV((it + 1) * 64, buf ^ 1);
            cp_commit();
            cp_wait<1>();
        } else {
            cp_wait<0>();
        }
        __syncthreads();

        const __nv_bfloat16* cK = sK + buf * 64 * FA_LD;
        const __nv_bfloat16* cV = sV + buf * 64 * FA_LD;

        float s[8][4];
        #pragma unroll
        for (int j = 0; j < 8; j++)
            #pragma unroll
            for (int q = 0; q < 4; q++) s[j][q] = 0.f;
        #pragma unroll
        for (int t = 0; t < 4; t++) {
            #pragma unroll
            for (int jp = 0; jp < 4; jp++) {
                uint32_t kf[4];
                int r = jp * 16 + (g >> 1) * 8 + i8;
                int c = t * 16 + (g & 1) * 8;
                ldsm4(kf, &cK[r * FA_LD + c]);
                mma16(s[2 * jp],     qf[t], &kf[0]);
                mma16(s[2 * jp + 1], qf[t], &kf[2]);
            }
        }

        float tmA = s[0][0], tmB = s[0][2];
        #pragma unroll
        for (int j = 0; j < 8; j++) {
            tmA = fmaxf(tmA, fmaxf(s[j][0], s[j][1]));
            tmB = fmaxf(tmB, fmaxf(s[j][2], s[j][3]));
        }
        tmA = fmaxf(tmA, __shfl_xor_sync(0xffffffffu, tmA, 1));
        tmA = fmaxf(tmA, __shfl_xor_sync(0xffffffffu, tmA, 2));
        tmB = fmaxf(tmB, __shfl_xor_sync(0xffffffffu, tmB, 1));
        tmB = fmaxf(tmB, __shfl_xor_sync(0xffffffffu, tmB, 2));

        float nmA = fmaxf(mA, tmA), nmB = fmaxf(mB, tmB);
        float sclA = __expf(mA - nmA), sclB = __expf(mB - nmB);
        mA = nmA; mB = nmB;

        float sumA = 0.f, sumB = 0.f;
        #pragma unroll
        for (int j = 0; j < 8; j++) {
            s[j][0] = __expf(s[j][0] - nmA);
            s[j][1] = __expf(s[j][1] - nmA);
            s[j][2] = __expf(s[j][2] - nmB);
            s[j][3] = __expf(s[j][3] - nmB);
            sumA += s[j][0] + s[j][1];
            sumB += s[j][2] + s[j][3];
        }
        sumA += __shfl_xor_sync(0xffffffffu, sumA, 1);
        sumA += __shfl_xor_sync(0xffffffffu, sumA, 2);
        sumB += __shfl_xor_sync(0xffffffffu, sumB, 1);
        sumB += __shfl_xor_sync(0xffffffffu, sumB, 2);
        lA = lA * sclA + sumA;
        lB = lB * sclB + sumB;

        #pragma unroll
        for (int j = 0; j < 8; j++) {
            oacc[j][0] *= sclA; oacc[j][1] *= sclA;
            oacc[j][2] *= sclB; oacc[j][3] *= sclB;
        }

        #pragma unroll
        for (int t = 0; t < 4; t++) {
            uint32_t pa[4];
            pa[0] = packbf(s[2 * t][0],     s[2 * t][1]);
            pa[1] = packbf(s[2 * t][2],     s[2 * t][3]);
            pa[2] = packbf(s[2 * t + 1][0], s[2 * t + 1][1]);
            pa[3] = packbf(s[2 * t + 1][2], s[2 * t + 1][3]);
            #pragma unroll
            for (int jp = 0; jp < 4; jp++) {
                uint32_t vf[4];
                int r = t * 16 + (g & 1) * 8 + i8;
                int c = jp * 16 + (g >> 1) * 8;
                ldsm4t(vf, &cV[r * FA_LD + c]);
                mma16(oacc[2 * jp],     pa, &vf[0]);
                mma16(oacc[2 * jp + 1], pa, &vf[2]);
            }
        }
    }

    const float invA = 1.f / lA, invB = 1.f / lB;
    const size_t rowA = (size_t)(b * SEQ + q0 + w * 16 + lr);
    #pragma unroll
    for (int j = 0; j < 8; j++) {
        int col = h * 64 + j * 8 + 2 * lq;
        *(uint32_t*)&C[rowA * 1024 + col] =
            packbf(oacc[j][0] * invA, oacc[j][1] * invA);
        *(uint32_t*)&C[(rowA + 8) * 1024 + col] =
            packbf(oacc[j][2] * invB, oacc[j][3] * invB);
    }
}

// ---------------------------------------------------------------------------
// out = LayerNorm(X + R) * g + b; optional bf16 shadow.
// ---------------------------------------------------------------------------
__global__ void __launch_bounds__(256)
add_ln1024(const float* __restrict__ X, const float* __restrict__ R,
           const float* __restrict__ gam, const float* __restrict__ bet,
           float* __restrict__ O, __nv_bfloat16* __restrict__ Ob)
{
    size_t row = blockIdx.x;
    const int t = threadIdx.x;
    float4 a = ((const float4*)(X + row * 1024))[t];
    float4 r = ((const float4*)(R + row * 1024))[t];
    float4 s;
    s.x = a.x + r.x; s.y = a.y + r.y; s.z = a.z + r.z; s.w = a.w + r.w;
    float sum = s.x + s.y + s.z + s.w;
    float sq  = s.x * s.x + s.y * s.y + s.z * s.z + s.w * s.w;
    sum = bred_sum(sum);
    sq  = bred_sum(sq);
    const float mu  = sum * (1.f / 1024.f);
    const float var = sq * (1.f / 1024.f) - mu * mu;
    const float rs  = rsqrtf(var + 1e-5f);
    float4 g4 = ((const float4*)gam)[t];
    float4 b4 = ((const float4*)bet)[t];
    float4 o;
    o.x = (s.x - mu) * rs * g4.x + b4.x;
    o.y = (s.y - mu) * rs * g4.y + b4.y;
    o.z = (s.z - mu) * rs * g4.z + b4.z;
    o.w = (s.w - mu) * rs * g4.w + b4.w;
    ((float4*)(O + row * 1024))[t] = o;
    if (Ob) {
        uint2 u;
        u.x = packbf(o.x, o.y);
        u.y = packbf(o.z, o.w);
        ((uint2*)(Ob + row * 1024))[t] = u;
    }
}

// ---------------------------------------------------------------------------
// Launch
// ---------------------------------------------------------------------------
extern "C" void kernel_launch(void* const* d_in, const int* in_sizes, int n_in,
                              void* d_out, int out_size)
{
    (void)in_sizes; (void)n_in; (void)out_size;
    const float* src = (const float*)d_in[0];
    const float* Wq  = (const float*)d_in[1];
    const float* bq  = (const float*)d_in[2];
    const float* Wk  = (const float*)d_in[3];
    const float* bk  = (const float*)d_in[4];
    const float* Wv  = (const float*)d_in[5];
    const float* bv  = (const float*)d_in[6];
    const float* Wo  = (const float*)d_in[7];
    const float* bo  = (const float*)d_in[8];
    const float* W1  = (const float*)d_in[9];
    const float* b1  = (const float*)d_in[10];
    const float* W2  = (const float*)d_in[11];
    const float* b2  = (const float*)d_in[12];
    const float* ln1g = (const float*)d_in[13];
    const float* ln1b = (const float*)d_in[14];
    const float* ln2g = (const float*)d_in[15];
    const float* ln2b = (const float*)d_in[16];
    float* out = (float*)d_out;

    __nv_bfloat16 *srcB, *Wqkv, *WoB, *W1B, *W2B, *QKV, *C, *X1B, *H;
    float *bqkv, *AO, *X1, *FF;
    cudaGetSymbolAddress((void**)&srcB, g_srcB);
    cudaGetSymbolAddress((void**)&Wqkv, g_Wqkv);
    cudaGetSymbolAddress((void**)&bqkv, g_bqkv);
    cudaGetSymbolAddress((void**)&WoB,  g_WoB);
    cudaGetSymbolAddress((void**)&W1B,  g_W1B);
    cudaGetSymbolAddress((void**)&W2B,  g_W2B);
    cudaGetSymbolAddress((void**)&QKV,  g_QKV);
    cudaGetSymbolAddress((void**)&C,    g_C);
    cudaGetSymbolAddress((void**)&X1B,  g_X1B);
    cudaGetSymbolAddress((void**)&H,    g_H);
    cudaGetSymbolAddress((void**)&AO,   g_AO);
    cudaGetSymbolAddress((void**)&X1,   g_X1);
    cudaGetSymbolAddress((void**)&FF,   g_FF);

    auto gF  = gemm_b2<false, false>;   // fp32 out
    auto gB  = gemm_b2<false, true>;    // bf16 out
    auto gRB = gemm_b2<true,  true>;    // relu + bf16 out
    cudaFuncSetAttribute(gF,  cudaFuncAttributeMaxDynamicSharedMemorySize, G2_SMEM);
    cudaFuncSetAttribute(gB,  cudaFuncAttributeMaxDynamicSharedMemorySize, G2_SMEM);
    cudaFuncSetAttribute(gRB, cudaFuncAttributeMaxDynamicSharedMemorySize, G2_SMEM);
    cudaFuncSetAttribute(fa_kernel, cudaFuncAttributeMaxDynamicSharedMemorySize, FA_SMEM);

    // 0-4: prep (launch #5 = QKV GEMM for ncu -s 5)
    bias_qkv<<<12, 256>>>(bq, bk, bv, bqkv);
    cvt_bf16<<<256, 256>>>(src, srcB, TOK * DMODEL / 4, 1.f);
    cvt_cat3<<<dim3(64, 3), 256>>>(Wq, Wk, Wv, Wqkv);
    cvt_bf16<<<64, 256>>>(Wo, WoB, DMODEL * DMODEL / 4, 1.f);
    cvt_bf16<<<128, 256>>>(W1, W1B, DMODEL * DFFN / 4, 1.f);

    // 5: fused QKV projection -> bf16 [4096][3072]
    gB<<<dim3(12, 32), 256, G2_SMEM>>>(srcB, Wqkv, bqkv, QKV, 1024, 1024, 3072, 3072);

    // W2 convert (independent)
    cvt_bf16<<<128, 256>>>(W2, W2B, DFFN * DMODEL / 4, 1.f);

    // Fused attention -> bf16 ctx
    fa_kernel<<<dim3(8, 32), dim3(512), FA_SMEM>>>(QKV, C, 3072);

    // attn_out = ctx * Wo + bo (fp32)
    gF<<<dim3(4, 32), 256, G2_SMEM>>>(C, WoB, bo, AO, 1024, 1024, 1024, 1024);

    // x1 = LN(src + attn_out)
    add_ln1024<<<4096, 256>>>(src, AO, ln1g, ln1b, X1, X1B);

    // h = relu(x1 * W1 + b1) -> bf16
    gRB<<<dim3(16, 32), 256, G2_SMEM>>>(X1B, W1B, b1, H, 1024, 1024, 4096, 4096);

    // ff = h * W2 + b2 (fp32)
    gF<<<dim3(4, 32), 256, G2_SMEM>>>(H, W2B, b2, FF, 4096, 4096, 1024, 1024);

    // out = LN(x1 + ff)
    add_ln1024<<<4096, 256>>>(X1, FF, ln2g, ln2b, out, nullptr);
}

// round 10
// speedup vs baseline: 1.0296x; 1.0296x over previous
#include <cuda_runtime.h>
#include <cuda_bf16.h>
#include <cstdint>

// Problem constants
static constexpr int TOK    = 4096;   // B*S
static constexpr int SEQ    = 2048;
static constexpr int DMODEL = 1024;
static constexpr int DFFN   = 4096;

// ---------------------------------------------------------------------------
// Device scratch (allocation-free rule: __device__ globals)
// ---------------------------------------------------------------------------
__device__ __nv_bfloat16 g_srcB [(size_t)TOK * DMODEL];
__device__ __nv_bfloat16 g_Wqkv [(size_t)DMODEL * 3 * DMODEL];  // [1024][3072]
__device__ float         g_bqkv [3 * DMODEL];
__device__ __nv_bfloat16 g_WoB  [(size_t)DMODEL * DMODEL];
__device__ __nv_bfloat16 g_W1B  [(size_t)DMODEL * DFFN];
__device__ __nv_bfloat16 g_W2B  [(size_t)DFFN * DMODEL];
__device__ __nv_bfloat16 g_QKV  [(size_t)TOK * 3 * DMODEL];     // [4096][3072]
__device__ __nv_bfloat16 g_C    [(size_t)TOK * DMODEL];         // ctx (bf16)
__device__ __nv_bfloat16 g_X1B  [(size_t)TOK * DMODEL];         // bf16 LN1 out
__device__ __nv_bfloat16 g_H    [(size_t)TOK * DFFN];           // bf16 relu
__device__ float g_AO[(size_t)TOK * DMODEL];                    // fp32 attn_out
__device__ float g_X1[(size_t)TOK * DMODEL];                    // fp32 LN1 out
__device__ float g_FF[(size_t)TOK * DMODEL];                    // fp32 ff out

// Single dynamic-smem declaration shared by all kernels
extern __shared__ __align__(16) char dsmem[];

// ---------------------------------------------------------------------------
// Helpers
// ---------------------------------------------------------------------------
__device__ __forceinline__ uint32_t packbf(float lo, float hi) {
    uint32_t r;
    asm("cvt.rn.bf16x2.f32 %0, %1, %2;" : "=r"(r) : "f"(hi), "f"(lo));
    return r;
}
__device__ __forceinline__ void cp16(void* s, const void* g) {
    uint32_t sa = (uint32_t)__cvta_generic_to_shared(s);
    asm volatile("cp.async.cg.shared.global [%0], [%1], 16;" :: "r"(sa), "l"(g));
}
__device__ __forceinline__ void cp_commit() { asm volatile("cp.async.commit_group;"); }
template <int N> __device__ __forceinline__ void cp_wait() {
    asm volatile("cp.async.wait_group %0;" :: "n"(N));
}
__device__ __forceinline__ void ldsm4(uint32_t* r, const void* p) {
    uint32_t a = (uint32_t)__cvta_generic_to_shared(p);
    asm volatile("ldmatrix.sync.aligned.m8n8.x4.shared.b16 {%0,%1,%2,%3}, [%4];"
                 : "=r"(r[0]), "=r"(r[1]), "=r"(r[2]), "=r"(r[3]) : "r"(a));
}
__device__ __forceinline__ void ldsm4t(uint32_t* r, const void* p) {
    uint32_t a = (uint32_t)__cvta_generic_to_shared(p);
    asm volatile("ldmatrix.sync.aligned.m8n8.x4.trans.shared.b16 {%0,%1,%2,%3}, [%4];"
                 : "=r"(r[0]), "=r"(r[1]), "=r"(r[2]), "=r"(r[3]) : "r"(a));
}
__device__ __forceinline__ void mma16(float* c, const uint32_t* a, const uint32_t* b) {
    asm volatile(
        "mma.sync.aligned.m16n8k16.row.col.f32.bf16.bf16.f32 "
        "{%0,%1,%2,%3},{%4,%5,%6,%7},{%8,%9},{%0,%1,%2,%3};"
        : "+f"(c[0]), "+f"(c[1]), "+f"(c[2]), "+f"(c[3])
        : "r"(a[0]), "r"(a[1]), "r"(a[2]), "r"(a[3]), "r"(b[0]), "r"(b[1]));
}
__device__ __forceinline__ float bred_sum(float v) {
    __shared__ float sh[8];
    #pragma unroll
    for (int o = 16; o > 0; o >>= 1) v += __shfl_xor_sync(0xffffffffu, v, o);
    if ((threadIdx.x & 31) == 0) sh[threadIdx.x >> 5] = v;
    __syncthreads();
    float r = sh[0];
    #pragma unroll
    for (int i = 1; i < 8; i++) r += sh[i];
    __syncthreads();
    return r;
}

// ---------------------------------------------------------------------------
// Converters
// ---------------------------------------------------------------------------
__global__ void __launch_bounds__(256)
cvt_bf16(const float* __restrict__ in, __nv_bfloat16* __restrict__ out,
         int n4, float scale)
{
    for (int i = blockIdx.x * 256 + threadIdx.x; i < n4; i += gridDim.x * 256) {
        float4 v = ((const float4*)in)[i];
        uint2 u;
        u.x = packbf(v.x * scale, v.y * scale);
        u.y = packbf(v.z * scale, v.w * scale);
        ((uint2*)out)[i] = u;
    }
}
// Concatenate Wq|Wk|Wv ([1024][1024] each) into [1024][3072] bf16 (Wq scaled).
__global__ void __launch_bounds__(256)
cvt_cat3(const float* __restrict__ Wq, const float* __restrict__ Wk,
         const float* __restrict__ Wv, __nv_bfloat16* __restrict__ out)
{
    const int z = blockIdx.y;
    const float* in = (z == 0) ? Wq : (z == 1) ? Wk : Wv;
    const float scale = (z == 0) ? 0.125f : 1.f;
    for (int i = blockIdx.x * 256 + threadIdx.x; i < 1024 * 256; i += gridDim.x * 256) {
        int r = i >> 8, c4 = i & 255;
        float4 v = ((const float4*)(in + (size_t)r * 1024))[c4];
        uint2 u;
        u.x = packbf(v.x * scale, v.y * scale);
        u.y = packbf(v.z * scale, v.w * scale);
        ((uint2*)(out + (size_t)r * 3072 + z * 1024))[c4] = u;
    }
}
__global__ void __launch_bounds__(256)
bias_qkv(const float* __restrict__ bq, const float* __restrict__ bk,
         const float* __restrict__ bv, float* __restrict__ o)
{
    int i = blockIdx.x * 256 + threadIdx.x;
    if (i < 1024)       o[i] = bq[i] * 0.125f;
    else if (i < 2048)  o[i] = bk[i - 1024];
    else if (i < 3072)  o[i] = bv[i - 2048];
}

// ---------------------------------------------------------------------------
// BF16 GEMM (round-5 tile, 3-stage ring).
// C[M,N] = epi(A[M,K]*B + bias). A row-major, B [K,N] row-major.
// BM=128 BN=128 BK=64, 8 warps (WT 32x64), 2 CTAs/SM, 3-stage cp.async.
// ---------------------------------------------------------------------------
static constexpr int G_LDA = 72;    // bf16 row stride A (144 B)
static constexpr int G_LDB = 136;   // bf16 row stride B (272 B)
static constexpr int G_ASZ = 128 * G_LDA;
static constexpr int G_BSZ = 64 * G_LDB;
static constexpr int G_STAGE = G_ASZ + G_BSZ;       // elements
static constexpr int G_SMEM  = 3 * G_STAGE * 2;     // 107520 B

template <bool RELU, bool OBF>
__global__ void __launch_bounds__(256, 2)
gemm_b(const __nv_bfloat16* __restrict__ A, const __nv_bfloat16* __restrict__ B,
       const float* __restrict__ bias, void* __restrict__ Cv,
       int Kdim, int lda, int ldb, int ldc)
{
    __nv_bfloat16* smem = (__nv_bfloat16*)dsmem;

    const int m0 = blockIdx.y * 128, n0 = blockIdx.x * 128;
    const int tid = threadIdx.x, w = tid >> 5, l = tid & 31;
    const int wm = (w & 3) * 32, wn = (w >> 2) * 64;
    const int g = l >> 3, i8 = l & 7;
    const int lr = l >> 2, lq = l & 3;

    float acc[2][8][4];
    #pragma unroll
    for (int i = 0; i < 2; i++)
        #pragma unroll
        for (int j = 0; j < 8; j++)
            #pragma unroll
            for (int q = 0; q < 4; q++) acc[i][j][q] = 0.f;

    const int NS = Kdim / 64;

    auto load_stage = [&](int s) {
        __nv_bfloat16* dA = smem + (s % 3) * G_STAGE;
        __nv_bfloat16* dB = dA + G_ASZ;
        {   // A tile [128][64]
            const __nv_bfloat16* gA = A + (size_t)m0 * lda + s * 64;
            #pragma unroll
            for (int i = 0; i < 4; i++) {
                int idx = tid + i * 256;
                int r = idx >> 3, c = (idx & 7) * 8;
                cp16(&dA[r * G_LDA + c], gA + (size_t)r * lda + c);
            }
        }
        {   // B tile [64][128]
            const __nv_bfloat16* gB = B + (size_t)s * 64 * ldb + n0;
            #pragma unroll
            for (int i = 0; i < 4; i++) {
                int idx = tid + i * 256;
                int r = idx >> 4, c = (idx & 15) * 8;
                cp16(&dB[r * G_LDB + c], gB + (size_t)r * ldb + c);
            }
        }
    };

    load_stage(0); cp_commit();
    load_stage(1); cp_commit();
    load_stage(2); cp_commit();

    for (int s = 0; s < NS; s++) {
        cp_wait<2>();
        __syncthreads();

        const __nv_bfloat16* cA = smem + (s % 3) * G_STAGE;
        const __nv_bfloat16* cB = cA + G_ASZ;
        #pragma unroll
        for (int t = 0; t < 4; t++) {
            uint32_t af[2][4], bf[4][4];
            #pragma unroll
            for (int i = 0; i < 2; i++) {
                int r = wm + i * 16 + (g & 1) * 8 + i8;
                int c = t * 16 + (g >> 1) * 8;
                ldsm4(af[i], &cA[r * G_LDA + c]);
            }
            #pragma unroll
            for (int p = 0; p < 4; p++) {
                int r = t * 16 + (g & 1) * 8 + i8;
                int c = wn + p * 16 + (g >> 1) * 8;
                ldsm4t(bf[p], &cB[r * G_LDB + c]);
            }
            #pragma unroll
            for (int i = 0; i < 2; i++)
                #pragma unroll
                for (int p = 0; p < 4; p++) {
                    mma16(acc[i][2 * p],     af[i], &bf[p][0]);
                    mma16(acc[i][2 * p + 1], af[i], &bf[p][2]);
                }
        }
        __syncthreads();
        if (s + 3 < NS) load_stage(s + 3);
        cp_commit();
    }

    // Epilogue
    #pragma unroll
    for (int i = 0; i < 2; i++) {
        #pragma unroll
        for (int j = 0; j < 8; j++) {
            int r = m0 + wm + i * 16 + lr;
            int c = n0 + wn + j * 8 + lq * 2;
            float b0 = bias[c], b1 = bias[c + 1];
            float v0 = acc[i][j][0] + b0;
            float v1 = acc[i][j][1] + b1;
            float v2 = acc[i][j][2] + b0;
            float v3 = acc[i][j][3] + b1;
            if constexpr (RELU) {
                v0 = fmaxf(v0, 0.f); v1 = fmaxf(v1, 0.f);
                v2 = fmaxf(v2, 0.f); v3 = fmaxf(v3, 0.f);
            }
            if constexpr (OBF) {
                __nv_bfloat16* Cb = (__nv_bfloat16*)Cv;
                *(uint32_t*)&Cb[(size_t)r * ldc + c]       = packbf(v0, v1);
                *(uint32_t*)&Cb[(size_t)(r + 8) * ldc + c] = packbf(v2, v3);
            } else {
                float* Cf = (float*)Cv;
                *(float2*)&Cf[(size_t)r * ldc + c]       = make_float2(v0, v1);
                *(float2*)&Cf[(size_t)(r + 8) * ldc + c] = make_float2(v2, v3);
            }
        }
    }
}

// ---------------------------------------------------------------------------
// Fused flash attention (bf16). 256 threads / 8 warps, 128 q-rows per block,
// 2 blocks/SM. Warp w owns rows [16w,16w+16). P stays in registers.
// ---------------------------------------------------------------------------
static constexpr int FA_LD = 72;
static constexpr int FA_SMEM = (4 * 64 * FA_LD + 128 * FA_LD) * 2;   // 55296 B

__global__ void __launch_bounds__(256, 2)
fa_kernel(const __nv_bfloat16* __restrict__ QKV, __nv_bfloat16* __restrict__ C, int ldq)
{
    constexpr int NIT = SEQ / 64;
    __nv_bfloat16* smem = (__nv_bfloat16*)dsmem;
    __nv_bfloat16* sK = smem;
    __nv_bfloat16* sV = smem + 2 * 64 * FA_LD;
    __nv_bfloat16* sQ = smem + 4 * 64 * FA_LD;

    const int z = blockIdx.y;
    const int b = z >> 4, h = z & 15;
    const int q0 = blockIdx.x * 128;
    const __nv_bfloat16* Qg = QKV + (size_t)(b * SEQ + q0) * ldq + h * 64;
    const __nv_bfloat16* Kg = QKV + (size_t)(b * SEQ) * ldq + 1024 + h * 64;
    const __nv_bfloat16* Vg = QKV + (size_t)(b * SEQ) * ldq + 2048 + h * 64;

    const int tid = threadIdx.x, w = tid >> 5, l = tid & 31;
    const int g = l >> 3, i8 = l & 7;
    const int lr = l >> 2, lq = l & 3;

    auto loadKV = [&](int n0, int buf) {
        __nv_bfloat16* dK = sK + buf * 64 * FA_LD;
        __nv_bfloat16* dV = sV + buf * 64 * FA_LD;
        #pragma unroll
        for (int i = 0; i < 2; i++) {       // 64 rows x 8 chunks = 512 / 256 thr
            int idx = tid + i * 256;
            int r = idx >> 3, c = (idx & 7) * 8;
            cp16(&dK[r * FA_LD + c], Kg + (size_t)(n0 + r) * ldq + c);
            cp16(&dV[r * FA_LD + c], Vg + (size_t)(n0 + r) * ldq + c);
        }
    };

    #pragma unroll
    for (int i = 0; i < 4; i++) {           // 128 rows x 8 chunks = 1024
        int idx = tid + i * 256;
        int r = idx >> 3, c = (idx & 7) * 8;
        cp16(&sQ[r * FA_LD + c], Qg + (size_t)r * ldq + c);
    }
    cp_commit();
    loadKV(0, 0);
    cp_commit();

    cp_wait<1>();
    __syncthreads();

    uint32_t qf[4][4];
    #pragma unroll
    for (int t = 0; t < 4; t++) {
        int r = w * 16 + (g & 1) * 8 + i8;
        int c = t * 16 + (g >> 1) * 8;
        ldsm4(qf[t], &sQ[r * FA_LD + c]);
    }

    float oacc[8][4];
    #pragma unroll
    for (int j = 0; j < 8; j++)
        #pragma unroll
        for (int q = 0; q < 4; q++) oacc[j][q] = 0.f;
    float mA = -1e30f, mB = -1e30f, lA = 0.f, lB = 0.f;

    for (int it = 0; it < NIT; it++) {
        const int buf = it & 1;
        __syncthreads();
        if (it + 1 < NIT) {
            loadKV((it + 1) * 64, buf ^ 1);
            cp_commit();
            cp_wait<1>();
        } else {
            cp_wait<0>();
        }
        __syncthreads();

        const __nv_bfloat16* cK = sK + buf * 64 * FA_LD;
        const __nv_bfloat16* cV = sV + buf * 64 * FA_LD;

        float s[8][4];
        #pragma unroll
        for (int j = 0; j < 8; j++)
            #pragma unroll
            for (int q = 0; q < 4; q++) s[j][q] = 0.f;
        #pragma unroll
        for (int t = 0; t < 4; t++) {
            #pragma unroll
            for (int jp = 0; jp < 4; jp++) {
                uint32_t kf[4];
                int r = jp * 16 + (g >> 1) * 8 + i8;
                int c = t * 16 + (g & 1) * 8;
                ldsm4(kf, &cK[r * FA_LD + c]);
                mma16(s[2 * jp],     qf[t], &kf[0]);
                mma16(s[2 * jp + 1], qf[t], &kf[2]);
            }
        }

        float tmA = s[0][0], tmB = s[0][2];
        #pragma unroll
        for (int j = 0; j < 8; j++) {
            tmA = fmaxf(tmA, fmaxf(s[j][0], s[j][1]));
            tmB = fmaxf(tmB, fmaxf(s[j][2], s[j][3]));
        }
        tmA = fmaxf(tmA, __shfl_xor_sync(0xffffffffu, tmA, 1));
        tmA = fmaxf(tmA, __shfl_xor_sync(0xffffffffu, tmA, 2));
        tmB = fmaxf(tmB, __shfl_xor_sync(0xffffffffu, tmB, 1));
        tmB = fmaxf(tmB, __shfl_xor_sync(0xffffffffu, tmB, 2));

        float nmA = fmaxf(mA, tmA), nmB = fmaxf(mB, tmB);
        float sclA = __expf(mA - nmA), sclB = __expf(mB - nmB);
        mA = nmA; mB = nmB;

        float sumA = 0.f, sumB = 0.f;
        #pragma unroll
        for (int j = 0; j < 8; j++) {
            s[j][0] = __expf(s[j][0] - nmA);
            s[j][1] = __expf(s[j][1] - nmA);
            s[j][2] = __expf(s[j][2] - nmB);
            s[j][3] = __expf(s[j][3] - nmB);
            sumA += s[j][0] + s[j][1];
            sumB += s[j][2] + s[j][3];
        }
        sumA += __shfl_xor_sync(0xffffffffu, sumA, 1);
        sumA += __shfl_xor_sync(0xffffffffu, sumA, 2);
        sumB += __shfl_xor_sync(0xffffffffu, sumB, 1);
        sumB += __shfl_xor_sync(0xffffffffu, sumB, 2);
        lA = lA * sclA + sumA;
        lB = lB * sclB + sumB;

        #pragma unroll
        for (int j = 0; j < 8; j++) {
            oacc[j][0] *= sclA; oacc[j][1] *= sclA;
            oacc[j][2] *= sclB; oacc[j][3] *= sclB;
        }

        #pragma unroll
        for (int t = 0; t < 4; t++) {
            uint32_t pa[4];
            pa[0] = packbf(s[2 * t][0],     s[2 * t][1]);
            pa[1] = packbf(s[2 * t][2],     s[2 * t][3]);
            pa[2] = packbf(s[2 * t + 1][0], s[2 * t + 1][1]);
            pa[3] = packbf(s[2 * t + 1][2], s[2 * t + 1][3]);
            #pragma unroll
            for (int jp = 0; jp < 4; jp++) {
                uint32_t vf[4];
                int r = t * 16 + (g & 1) * 8 + i8;
                int c = jp * 16 + (g >> 1) * 8;
                ldsm4t(vf, &cV[r * FA_LD + c]);
                mma16(oacc[2 * jp],     pa, &vf[0]);
                mma16(oacc[2 * jp + 1], pa, &vf[2]);
            }
        }
    }

    const float invA = 1.f / lA, invB = 1.f / lB;
    const size_t rowA = (size_t)(b * SEQ + q0 + w * 16 + lr);
    #pragma unroll
    for (int j = 0; j < 8; j++) {
        int col = h * 64 + j * 8 + 2 * lq;
        *(uint32_t*)&C[rowA * 1024 + col] =
            packbf(oacc[j][0] * invA, oacc[j][1] * invA);
        *(uint32_t*)&C[(rowA + 8) * 1024 + col] =
            packbf(oacc[j][2] * invB, oacc[j][3] * invB);
    }
}

// ---------------------------------------------------------------------------
// out = LayerNorm(X + R) * g + b; optional bf16 shadow.
// ---------------------------------------------------------------------------
__global__ void __launch_bounds__(256)
add_ln1024(const float* __restrict__ X, const float* __restrict__ R,
           const float* __restrict__ gam, const float* __restrict__ bet,
           float* __restrict__ O, __nv_bfloat16* __restrict__ Ob)
{
    size_t row = blockIdx.x;
    const int t = threadIdx.x;
    float4 a = ((const float4*)(X + row * 1024))[t];
    float4 r = ((const float4*)(R + row * 1024))[t];
    float4 s;
    s.x = a.x + r.x; s.y = a.y + r.y; s.z = a.z + r.z; s.w = a.w + r.w;
    float sum = s.x + s.y + s.z + s.w;
    float sq  = s.x * s.x + s.y * s.y + s.z * s.z + s.w * s.w;
    sum = bred_sum(sum);
    sq  = bred_sum(sq);
    const float mu  = sum * (1.f / 1024.f);
    const float var = sq * (1.f / 1024.f) - mu * mu;
    const float rs  = rsqrtf(var + 1e-5f);
    float4 g4 = ((const float4*)gam)[t];
    float4 b4 = ((const float4*)bet)[t];
    float4 o;
    o.x = (s.x - mu) * rs * g4.x + b4.x;
    o.y = (s.y - mu) * rs * g4.y + b4.y;
    o.z = (s.z - mu) * rs * g4.z + b4.z;
    o.w = (s.w - mu) * rs * g4.w + b4.w;
    ((float4*)(O + row * 1024))[t] = o;
    if (Ob) {
        uint2 u;
        u.x = packbf(o.x, o.y);
        u.y = packbf(o.z, o.w);
        ((uint2*)(Ob + row * 1024))[t] = u;
    }
}

// ---------------------------------------------------------------------------
// Launch
// ---------------------------------------------------------------------------
extern "C" void kernel_launch(void* const* d_in, const int* in_sizes, int n_in,
                              void* d_out, int out_size)
{
    (void)in_sizes; (void)n_in; (void)out_size;
    const float* src = (const float*)d_in[0];
    const float* Wq  = (const float*)d_in[1];
    const float* bq  = (const float*)d_in[2];
    const float* Wk  = (const float*)d_in[3];
    const float* bk  = (const float*)d_in[4];
    const float* Wv  = (const float*)d_in[5];
    const float* bv  = (const float*)d_in[6];
    const float* Wo  = (const float*)d_in[7];
    const float* bo  = (const float*)d_in[8];
    const float* W1  = (const float*)d_in[9];
    const float* b1  = (const float*)d_in[10];
    const float* W2  = (const float*)d_in[11];
    const float* b2  = (const float*)d_in[12];
    const float* ln1g = (const float*)d_in[13];
    const float* ln1b = (const float*)d_in[14];
    const float* ln2g = (const float*)d_in[15];
    const float* ln2b = (const float*)d_in[16];
    float* out = (float*)d_out;

    __nv_bfloat16 *srcB, *Wqkv, *WoB, *W1B, *W2B, *QKV, *C, *X1B, *H;
    float *bqkv, *AO, *X1, *FF;
    cudaGetSymbolAddress((void**)&srcB, g_srcB);
    cudaGetSymbolAddress((void**)&Wqkv, g_Wqkv);
    cudaGetSymbolAddress((void**)&bqkv, g_bqkv);
    cudaGetSymbolAddress((void**)&WoB,  g_WoB);
    cudaGetSymbolAddress((void**)&W1B,  g_W1B);
    cudaGetSymbolAddress((void**)&W2B,  g_W2B);
    cudaGetSymbolAddress((void**)&QKV,  g_QKV);
    cudaGetSymbolAddress((void**)&C,    g_C);
    cudaGetSymbolAddress((void**)&X1B,  g_X1B);
    cudaGetSymbolAddress((void**)&H,    g_H);
    cudaGetSymbolAddress((void**)&AO,   g_AO);
    cudaGetSymbolAddress((void**)&X1,   g_X1);
    cudaGetSymbolAddress((void**)&FF,   g_FF);

    auto gF  = gemm_b<false, false>;   // fp32 out
    auto gB  = gemm_b<false, true>;    // bf16 out
    auto gRB = gemm_b<true,  true>;    // relu + bf16 out
    cudaFuncSetAttribute(gF,  cudaFuncAttributeMaxDynamicSharedMemorySize, G_SMEM);
    cudaFuncSetAttribute(gB,  cudaFuncAttributeMaxDynamicSharedMemorySize, G_SMEM);
    cudaFuncSetAttribute(gRB, cudaFuncAttributeMaxDynamicSharedMemorySize, G_SMEM);
    cudaFuncSetAttribute(fa_kernel, cudaFuncAttributeMaxDynamicSharedMemorySize, FA_SMEM);

    // 0-4: prep (launch #5 = QKV GEMM for ncu -s 5)
    bias_qkv<<<12, 256>>>(bq, bk, bv, bqkv);
    cvt_bf16<<<256, 256>>>(src, srcB, TOK * DMODEL / 4, 1.f);
    cvt_cat3<<<dim3(64, 3), 256>>>(Wq, Wk, Wv, Wqkv);
    cvt_bf16<<<64, 256>>>(Wo, WoB, DMODEL * DMODEL / 4, 1.f);
    cvt_bf16<<<128, 256>>>(W1, W1B, DMODEL * DFFN / 4, 1.f);

    // 5: fused QKV projection -> bf16 [4096][3072]
    gB<<<dim3(24, 32), 256, G_SMEM>>>(srcB, Wqkv, bqkv, QKV, 1024, 1024, 3072, 3072);

    // W2 convert (independent)
    cvt_bf16<<<128, 256>>>(W2, W2B, DFFN * DMODEL / 4, 1.f);

    // Fused attention -> bf16 ctx (128 q-rows/block, 2 blocks/SM)
    fa_kernel<<<dim3(16, 32), 256, FA_SMEM>>>(QKV, C, 3072);

    // attn_out = ctx * Wo + bo (fp32)
    gF<<<dim3(8, 32), 256, G_SMEM>>>(C, WoB, bo, AO, 1024, 1024, 1024, 1024);

    // x1 = LN(src + attn_out)
    add_ln1024<<<4096, 256>>>(src, AO, ln1g, ln1b, X1, X1B);

    // h = relu(x1 * W1 + b1) -> bf16
    gRB<<<dim3(32, 32), 256, G_SMEM>>>(X1B, W1B, b1, H, 1024, 1024, 4096, 4096);

    // ff = h * W2 + b2 (fp32)
    gF<<<dim3(8, 32), 256, G_SMEM>>>(H, W2B, b2, FF, 4096, 4096, 1024, 1024);

    // out = LN(x1 + ff)
    add_ln1024<<<4096, 256>>>(X1, FF, ln2g, ln2b, out, nullptr);
}